// round 16
// baseline (speedup 1.0000x reference)
#include <cuda_runtime.h>
#include <cuda_fp16.h>

// Problem constants
#define HEADS   8
#define DIMH    64
#define NSEQ    512
#define BATCH   32
#define DMODEL  512
#define BH      (BATCH*HEADS)        // 256
#define NQKV    (3*HEADS*DIMH)       // 1536
#define MROWS   (BATCH*NSEQ)         // 16384
#define ATT_SCALE 0.125f             // 64^-0.5

// ---------------- scratch (device globals; no cudaMalloc allowed) -----------
__device__ __align__(16) unsigned short g_q    [BH*NSEQ*DIMH];
__device__ __align__(16) unsigned short g_k    [BH*NSEQ*DIMH];
__device__ __align__(16) unsigned short g_vT   [BH*DIMH*NSEQ];    // [bh][d][n]
__device__ __align__(16) unsigned short g_ao   [BATCH*NSEQ*DMODEL];
__device__ __align__(16) unsigned short g_xh   [MROWS*DMODEL];
__device__ __align__(16) unsigned short g_wqkvT[NQKV*DMODEL];     // [N][K]
__device__ __align__(16) unsigned short g_woutT[DMODEL*DMODEL];   // [N][K]
__device__ __align__(16) unsigned short g_relh [1025*DIMH];

// ---------------------------------------------------------------------------
// helpers
// ---------------------------------------------------------------------------
__device__ __forceinline__ unsigned f2h2(float lo, float hi) {
    unsigned r;
    asm("cvt.rn.f16x2.f32 %0, %1, %2;" : "=r"(r) : "f"(hi), "f"(lo));
    return r;
}
__device__ __forceinline__ unsigned short f2h(float x) {
    unsigned short r;
    asm("cvt.rn.f16.f32 %0, %1;" : "=h"(r) : "f"(x));
    return r;
}

__device__ __forceinline__ void mma_f16(float c[4], const unsigned a[4],
                                        unsigned b0, unsigned b1) {
    asm volatile(
        "mma.sync.aligned.m16n8k16.row.col.f32.f16.f16.f32 "
        "{%0,%1,%2,%3}, {%4,%5,%6,%7}, {%8,%9}, {%0,%1,%2,%3};\n"
        : "+f"(c[0]), "+f"(c[1]), "+f"(c[2]), "+f"(c[3])
        : "r"(a[0]), "r"(a[1]), "r"(a[2]), "r"(a[3]), "r"(b0), "r"(b1));
}
#define MMAH mma_f16

__device__ __forceinline__ void cp16(void* smem_dst, const void* gsrc) {
    unsigned s = (unsigned)__cvta_generic_to_shared(smem_dst);
    asm volatile("cp.async.cg.shared.global [%0], [%1], 16;\n" :: "r"(s), "l"(gsrc));
}
__device__ __forceinline__ void cp_commit() {
    asm volatile("cp.async.commit_group;\n");
}
template<int Nq>
__device__ __forceinline__ void cp_wait() {
    asm volatile("cp.async.wait_group %0;\n" :: "n"(Nq));
}
__device__ __forceinline__ void bar_pair(int id) {
    asm volatile("bar.sync %0, 64;" :: "r"(id) : "memory");
}

// ============================================================================
// cvt_all: single launch handling all fp32->fp16 conversions (unchanged R15).
// ============================================================================
#define CVT_XB   8192
#define CVT_RB   65
#define CVT_QB   768
#define CVT_OB   256

__global__ void __launch_bounds__(256) cvt_all_kernel(
    const float* __restrict__ x, const float* __restrict__ rel,
    const float* __restrict__ Wq, const float* __restrict__ Wo)
{
    __shared__ float t[32][33];
    const int b   = blockIdx.x;
    const int tid = threadIdx.x;

    if (b < CVT_XB) {
        const int i = b * 256 + tid;
        float4 v = ((const float4*)x)[i];
        ((uint2*)g_xh)[i] = make_uint2(f2h2(v.x, v.y), f2h2(v.z, v.w));
        return;
    }
    if (b < CVT_XB + CVT_RB) {
        const int i = (b - CVT_XB) * 256 + tid;
        if (i < 1025 * DIMH / 4) {
            float4 v = ((const float4*)rel)[i];
            ((uint2*)g_relh)[i] = make_uint2(f2h2(v.x, v.y), f2h2(v.z, v.w));
        }
        return;
    }
    const float* src;
    unsigned short* dst;
    int R, C, bx, by;
    if (b < CVT_XB + CVT_RB + CVT_QB) {
        const int l = b - (CVT_XB + CVT_RB);
        src = Wq; dst = g_wqkvT; R = DMODEL; C = NQKV;
        bx = (l % 48) * 32; by = (l / 48) * 32;
    } else {
        const int l = b - (CVT_XB + CVT_RB + CVT_QB);
        src = Wo; dst = g_woutT; R = DMODEL; C = DMODEL;
        bx = (l % 16) * 32; by = (l / 16) * 32;
    }
    const int tx = tid & 31, ty = tid >> 5;
#pragma unroll
    for (int j = 0; j < 32; j += 8)
        t[ty + j][tx] = src[(size_t)(by + ty + j) * C + bx + tx];
    __syncthreads();
#pragma unroll
    for (int j = 0; j < 32; j += 8)
        dst[(size_t)(bx + ty + j) * R + by + tx] = f2h(t[tx][ty + j]);
}

// ============================================================================
// mm8: fp16 GEMM, occupancy-tuned. CTA tile 128(M) x 64(N), 128 threads,
// 4 warps (2m x 2n), warp tile 64x32 (mi=4, ni=4) -> acc 64 floats.
// BK=32 (2 k16 chunks, same K order as mm7 -> identical numerics),
// 4-stage cp.async ring. smem 61,440 B; __launch_bounds__(128,3): 3 CTAs/SM.
// ============================================================================
#define MM8_STAGE_W ((128 + 64) * 20)     // 3840 words
#define MM8_SMEM_BYTES (4 * MM8_STAGE_W * 4)

template<int N, int SCAT>   // SCAT: 0=bias epilogue, 1=qkv scatter
__global__ void __launch_bounds__(128, 3) mm8_kernel(
    const unsigned short* __restrict__ A, const unsigned short* __restrict__ Bt,
    const float* __restrict__ bias, float* __restrict__ Cout)
{
    constexpr int K = 512;
    constexpr int ITERS = 16;      // K / 32
    extern __shared__ unsigned sm[];

    const int tid  = threadIdx.x;
    const int w    = tid >> 5, lane = tid & 31;
    const int g    = lane >> 2, tig = lane & 3;
    const int wm   = w >> 1, wn = w & 1;
    const int bm   = blockIdx.y * 128;
    const int bn   = blockIdx.x * 64;

    auto issue = [&](int it) {
        const int s  = it & 3;
        const int k0 = it * 32;                 // halves
        unsigned* As = sm + s * MM8_STAGE_W;
        unsigned* Bs = As + 128 * 20;
        // A: 128 rows x 4 chunks = 512; 4 per thread
#pragma unroll
        for (int j = 0; j < 4; ++j) {
            const int c  = tid + j * 128;
            const int r  = c >> 2;
            const int ch = c & 3;
            cp16(&As[r * 20 + ch * 4], A + (size_t)(bm + r) * K + k0 + ch * 8);
        }
        // B: 64 rows x 4 chunks = 256; 2 per thread
#pragma unroll
        for (int j = 0; j < 2; ++j) {
            const int c  = tid + j * 128;
            const int r  = c >> 2;
            const int ch = c & 3;
            cp16(&Bs[r * 20 + ch * 4], Bt + (size_t)(bn + r) * K + k0 + ch * 8);
        }
    };

    float acc[4][4][4];
#pragma unroll
    for (int mi = 0; mi < 4; ++mi)
#pragma unroll
        for (int ni = 0; ni < 4; ++ni)
#pragma unroll
            for (int e = 0; e < 4; ++e) acc[mi][ni][e] = 0.f;

    issue(0); cp_commit();
    issue(1); cp_commit();
    issue(2); cp_commit();

    for (int it = 0; it < ITERS; ++it) {
        const int cur = it & 3;
        cp_wait<2>();
        __syncthreads();

        if (it + 3 < ITERS) issue(it + 3);
        cp_commit();

        const unsigned* As = sm + cur * MM8_STAGE_W;
        const unsigned* Bs = As + 128 * 20;
#pragma unroll
        for (int kt = 0; kt < 2; ++kt) {
            unsigned af[4][4];
#pragma unroll
            for (int mi = 0; mi < 4; ++mi) {
                const int base = wm * 64 + mi * 16;
                af[mi][0] = As[(base + g    ) * 20 + kt * 8 + tig    ];
                af[mi][1] = As[(base + g + 8) * 20 + kt * 8 + tig    ];
                af[mi][2] = As[(base + g    ) * 20 + kt * 8 + tig + 4];
                af[mi][3] = As[(base + g + 8) * 20 + kt * 8 + tig + 4];
            }
#pragma unroll
            for (int ni = 0; ni < 4; ++ni) {
                const int nr = wn * 32 + ni * 8 + g;
                const unsigned b0 = Bs[nr * 20 + kt * 8 + tig    ];
                const unsigned b1 = Bs[nr * 20 + kt * 8 + tig + 4];
#pragma unroll
                for (int mi = 0; mi < 4; ++mi)
                    MMAH(acc[mi][ni], af[mi], b0, b1);
            }
        }
    }

    // ---- epilogue ----
    if (SCAT) {
        const int which = bn >> 9;   // 64-col tiles never straddle q/k/v bounds
        if (which < 2) {
            unsigned short* dst = (which == 0) ? g_q : g_k;
#pragma unroll
            for (int mi = 0; mi < 4; ++mi) {
                const int r0  = bm + wm * 64 + mi * 16 + g;
                const int bb  = r0 >> 9;
                const int nn0 = r0 & 511;
#pragma unroll
                for (int ni = 0; ni < 4; ++ni) {
                    const int c  = bn + wn * 32 + ni * 8 + 2 * tig;
                    const int h  = (c & 511) >> 6;
                    const int dd = c & 63;
                    const size_t rowbase = (size_t)((bb << 3) + h) * NSEQ;
                    *(unsigned*)&dst[((rowbase + nn0    )) * DIMH + dd] =
                        f2h2(acc[mi][ni][0], acc[mi][ni][1]);
                    *(unsigned*)&dst[((rowbase + nn0 + 8)) * DIMH + dd] =
                        f2h2(acc[mi][ni][2], acc[mi][ni][3]);
                }
            }
        } else {
            // V: transpose 128x64 tile through smem, coalesced write to g_vT
            __syncthreads();
            unsigned short* tsm = (unsigned short*)sm;   // 64 x 136 halves
#pragma unroll
            for (int mi = 0; mi < 4; ++mi) {
                const int lr = wm * 64 + mi * 16 + g;
#pragma unroll
                for (int ni = 0; ni < 4; ++ni) {
                    const int lc = wn * 32 + ni * 8 + 2 * tig;
                    tsm[(lc    ) * 136 + lr    ] = f2h(acc[mi][ni][0]);
                    tsm[(lc + 1) * 136 + lr    ] = f2h(acc[mi][ni][1]);
                    tsm[(lc    ) * 136 + lr + 8] = f2h(acc[mi][ni][2]);
                    tsm[(lc + 1) * 136 + lr + 8] = f2h(acc[mi][ni][3]);
                }
            }
            __syncthreads();
            const int lc = tid >> 1;             // transposed row 0..63
            const int p  = tid & 1;              // n-half 0/1 (64 halves each)
            const int c  = bn + lc;
            const int h  = (c & 511) >> 6;
            const int dd = c & 63;
            const int bb = bm >> 9;
            const int nnb = (bm & 511) + p * 64;
            unsigned short* dstp =
                g_vT + ((size_t)((bb << 3) + h) * DIMH + dd) * NSEQ + nnb;
#pragma unroll
            for (int u = 0; u < 8; ++u)
                *(uint4*)(dstp + u * 8) = *(const uint4*)(tsm + lc * 136 + p * 64 + u * 8);
        }
    } else {
#pragma unroll
        for (int mi = 0; mi < 4; ++mi) {
            const int r = bm + wm * 64 + mi * 16 + g;
#pragma unroll
            for (int ni = 0; ni < 4; ++ni) {
                const int c = bn + wn * 32 + ni * 8 + 2 * tig;
                const float2 bv = *(const float2*)&bias[c];
                *(float2*)&Cout[(size_t)r * N + c] =
                    make_float2(acc[mi][ni][0] + bv.x, acc[mi][ni][1] + bv.y);
                *(float2*)&Cout[(size_t)(r + 8) * N + c] =
                    make_float2(acc[mi][ni][2] + bv.x, acc[mi][ni][3] + bv.y);
            }
        }
    }
}

// ============================================================================
// attn8: unchanged from R15 (passing; 3 CTAs/SM, early-V pipeline).
// ============================================================================
#define ATT8_SMEM_WORDS (2304 + 2304 + 4608 + 8448)
#define ATT8_SMEM_BYTES (ATT8_SMEM_WORDS * 4)

__global__ void __launch_bounds__(128, 3) attn8_kernel()
{
    extern __shared__ unsigned smu[];
    unsigned* rels  = smu;                    // 64 x 36 (Q staging alias)
    unsigned* ks    = smu + 2304;             // 64 x 36 (l-exchange alias)
    unsigned* vsbuf = smu + 4608;             // 2 x 64 x 36
    float*    pbs   = (float*)(smu + 9216);   // 64 x 132
    unsigned* ps    = (unsigned*)pbs;

    const int tid  = threadIdx.x;
    const int w    = tid >> 5;
    const int lane = tid & 31;
    const int g    = lane >> 2;
    const int tig  = lane & 3;
    const int wm   = w >> 1, wn = w & 1;

    const int bh = blockIdx.x;
    const int qb = blockIdx.y;
    const int i0 = qb * 64;
    const int rbase = wm * 32 + g;
    const int pbar  = wm + 1;

    const unsigned short* qg = g_q  + ((size_t)bh * NSEQ + i0) * DIMH;
    const unsigned short* kg = g_k  + (size_t)bh * NSEQ * DIMH;
    const unsigned short* vg = g_vT + (size_t)bh * DIMH * NSEQ;
    const unsigned short* rg = g_relh;

    auto copy_tile = [&](unsigned* dst, const unsigned short* src, int srcstride) {
#pragma unroll
        for (int k = 0; k < 4; ++k) {
            const int c  = tid + k * 128;
            const int r  = c >> 3;
            const int ch = c & 7;
            cp16(&dst[r * 36 + ch * 4], src + (size_t)r * srcstride + ch * 8);
        }
    };

    auto issue_kr = [&](int t) {
        const int j0 = t * 64;
        copy_tile(ks, kg + (size_t)j0 * DIMH, 64);
        copy_tile(rels, rg + (size_t)(i0 + 449 - j0) * DIMH, 64);
    };
    auto issue_v = [&](int t) {
        copy_tile(vsbuf + (t & 1) * 2304, vg + t * 64, NSEQ);
    };

    copy_tile(rels, qg, 64);
    cp_commit();
    cp_wait<0>();
    __syncthreads();

    unsigned qa[2][4][4];
#pragma unroll
    for (int mi = 0; mi < 2; ++mi) {
        const int r0 = rbase + mi * 16;
#pragma unroll
        for (int kt = 0; kt < 4; ++kt) {
            qa[mi][kt][0] = rels[ r0      * 36 + kt * 8 + tig    ];
            qa[mi][kt][1] = rels[(r0 + 8) * 36 + kt * 8 + tig    ];
            qa[mi][kt][2] = rels[ r0      * 36 + kt * 8 + tig + 4];
            qa[mi][kt][3] = rels[(r0 + 8) * 36 + kt * 8 + tig + 4];
        }
    }
    __syncthreads();

    {
        copy_tile(rels, rg + (size_t)(i0 + 513) * DIMH, 64);
        cp_commit();
        cp_wait<0>();
        __syncthreads();
#pragma unroll
        for (int nt = 0; nt < 4; ++nt) {
            float a0[4] = {0.f,0.f,0.f,0.f}, a1[4] = {0.f,0.f,0.f,0.f};
            const int dr = wn * 32 + nt * 8 + g;
#pragma unroll
            for (int kt = 0; kt < 4; ++kt) {
                const unsigned b0 = rels[dr * 36 + kt * 8 + tig    ];
                const unsigned b1 = rels[dr * 36 + kt * 8 + tig + 4];
                MMAH(a0, qa[0][kt], b0, b1);
                MMAH(a1, qa[1][kt], b0, b1);
            }
            const int col = 64 + wn * 32 + nt * 8 + 2 * tig;
            *(float2*)&pbs[(rbase     ) * 132 + col] = make_float2(a0[0], a0[1]);
            *(float2*)&pbs[(rbase +  8) * 132 + col] = make_float2(a0[2], a0[3]);
            *(float2*)&pbs[(rbase + 16) * 132 + col] = make_float2(a1[0], a1[1]);
            *(float2*)&pbs[(rbase + 24) * 132 + col] = make_float2(a1[2], a1[3]);
        }
    }
    __syncthreads();

    issue_kr(0);
    issue_v(0);
    cp_commit();

    float lsum[2][2] = {{0.f, 0.f}, {0.f, 0.f}};
    float o[2][8][4];
#pragma unroll
    for (int mi = 0; mi < 2; ++mi)
#pragma unroll
        for (int nt = 0; nt < 8; ++nt)
#pragma unroll
            for (int e = 0; e < 4; ++e) o[mi][nt][e] = 0.f;

    for (int t = 0; t < 8; ++t) {
        const int h = t & 1;
        const unsigned* vs = vsbuf + h * 2304;

        cp_wait<0>();
        __syncthreads();               // S2

        if (t + 1 < 8) { issue_v(t + 1); cp_commit(); }

#pragma unroll
        for (int nt = 0; nt < 4; ++nt) {
            float a0[4] = {0.f,0.f,0.f,0.f}, a1[4] = {0.f,0.f,0.f,0.f};
            const int dr = wn * 32 + nt * 8 + g;
#pragma unroll
            for (int kt = 0; kt < 4; ++kt) {
                const unsigned b0 = rels[dr * 36 + kt * 8 + tig    ];
                const unsigned b1 = rels[dr * 36 + kt * 8 + tig + 4];
                MMAH(a0, qa[0][kt], b0, b1);
                MMAH(a1, qa[1][kt], b0, b1);
            }
            const int col = h * 64 + wn * 32 + nt * 8 + 2 * tig;
            *(float2*)&pbs[(rbase     ) * 132 + col] = make_float2(a0[0], a0[1]);
            *(float2*)&pbs[(rbase +  8) * 132 + col] = make_float2(a0[2], a0[3]);
            *(float2*)&pbs[(rbase + 16) * 132 + col] = make_float2(a1[0], a1[1]);
            *(float2*)&pbs[(rbase + 24) * 132 + col] = make_float2(a1[2], a1[3]);
        }

        float s[2][4][4];
#pragma unroll
        for (int nt = 0; nt < 4; ++nt) {
            const int jr = wn * 32 + nt * 8 + g;
#pragma unroll
            for (int mi = 0; mi < 2; ++mi)
                s[mi][nt][0] = s[mi][nt][1] = s[mi][nt][2] = s[mi][nt][3] = 0.f;
#pragma unroll
            for (int kt = 0; kt < 4; ++kt) {
                const unsigned b0 = ks[jr * 36 + kt * 8 + tig    ];
                const unsigned b1 = ks[jr * 36 + kt * 8 + tig + 4];
                MMAH(s[0][nt], qa[0][kt], b0, b1);
                MMAH(s[1][nt], qa[1][kt], b0, b1);
            }
        }
        __syncthreads();               // S3

        if (t + 1 < 8) issue_kr(t + 1);
        cp_commit();

#pragma unroll
        for (int mi = 0; mi < 2; ++mi) {
            const int iA = rbase + mi * 16;
            const int iB = iA + 8;
#pragma unroll
            for (int nt = 0; nt < 4; ++nt) {
                const int jj = wn * 32 + nt * 8 + 2 * tig;
                const int oA0 = iA - jj + 63, oA1 = oA0 - 1;
                const int oB0 = iB - jj + 63, oB1 = oB0 - 1;
                const int pA0 = ((h ^ (oA0 >> 6)) << 6) | (oA0 & 63);
                const int pA1 = ((h ^ (oA1 >> 6)) << 6) | (oA1 & 63);
                const int pB0 = ((h ^ (oB0 >> 6)) << 6) | (oB0 & 63);
                const int pB1 = ((h ^ (oB1 >> 6)) << 6) | (oB1 & 63);
                float e0 = __expf((s[mi][nt][0] + pbs[iA * 132 + pA0]) * ATT_SCALE);
                float e1 = __expf((s[mi][nt][1] + pbs[iA * 132 + pA1]) * ATT_SCALE);
                float e2 = __expf((s[mi][nt][2] + pbs[iB * 132 + pB0]) * ATT_SCALE);
                float e3 = __expf((s[mi][nt][3] + pbs[iB * 132 + pB1]) * ATT_SCALE);
                s[mi][nt][0] = e0; s[mi][nt][1] = e1;
                s[mi][nt][2] = e2; s[mi][nt][3] = e3;
                lsum[mi][0] += e0 + e1;
                lsum[mi][1] += e2 + e3;
            }
        }
        bar_pair(pbar);                // S4

        const int pc0 = (h ^ 1) * 64;
#pragma unroll
        for (int mi = 0; mi < 2; ++mi) {
            const int iA = rbase + mi * 16;
            const int iB = iA + 8;
#pragma unroll
            for (int nt = 0; nt < 4; ++nt) {
                const int widx = pc0 + wn * 16 + nt * 4 + tig;
                ps[iA * 132 + widx] = f2h2(s[mi][nt][0], s[mi][nt][1]);
                ps[iB * 132 + widx] = f2h2(s[mi][nt][2], s[mi][nt][3]);
            }
        }
        bar_pair(pbar);                // S5

#pragma unroll
        for (int kt = 0; kt < 4; ++kt) {
            unsigned pa[2][4];
#pragma unroll
            for (int mi = 0; mi < 2; ++mi) {
                const int iA = rbase + mi * 16;
                const int iB = iA + 8;
                pa[mi][0] = ps[iA * 132 + pc0 + kt * 8 + tig    ];
                pa[mi][1] = ps[iB * 132 + pc0 + kt * 8 + tig    ];
                pa[mi][2] = ps[iA * 132 + pc0 + kt * 8 + tig + 4];
                pa[mi][3] = ps[iB * 132 + pc0 + kt * 8 + tig + 4];
            }
#pragma unroll
            for (int nt = 0; nt < 8; ++nt) {
                const int dr = nt * 8 + g;
                const unsigned b0 = vs[dr * 36 + kt * 8 + tig    ];
                const unsigned b1 = vs[dr * 36 + kt * 8 + tig + 4];
                MMAH(o[0][nt], pa[0], b0, b1);
                MMAH(o[1][nt], pa[1], b0, b1);
            }
        }
    }

#pragma unroll
    for (int mi = 0; mi < 2; ++mi)
#pragma unroll
        for (int hf = 0; hf < 2; ++hf) {
            float v = lsum[mi][hf];
            v += __shfl_xor_sync(0xffffffffu, v, 1);
            v += __shfl_xor_sync(0xffffffffu, v, 2);
            lsum[mi][hf] = v;
        }

    __syncthreads();
    float* lsm = (float*)ks;
    if (tig == 0) {
#pragma unroll
        for (int mi = 0; mi < 2; ++mi) {
            lsm[(rbase + mi * 16    ) * 2 + wn] = lsum[mi][0];
            lsm[(rbase + mi * 16 + 8) * 2 + wn] = lsum[mi][1];
        }
    }
    __syncthreads();

    const int bb = bh >> 3, hh = bh & 7;
#pragma unroll
    for (int mi = 0; mi < 2; ++mi) {
        const int iA = rbase + mi * 16;
        const int iB = iA + 8;
        const float ilA = 1.f / (lsm[iA * 2] + lsm[iA * 2 + 1]);
        const float ilB = 1.f / (lsm[iB * 2] + lsm[iB * 2 + 1]);
        unsigned short* baseA = g_ao + ((size_t)bb * NSEQ + (i0 + iA)) * DMODEL + hh * DIMH;
        unsigned short* baseB = g_ao + ((size_t)bb * NSEQ + (i0 + iB)) * DMODEL + hh * DIMH;
#pragma unroll
        for (int nt = 0; nt < 8; ++nt) {
            const int c = nt * 8 + 2 * tig;
            *(unsigned*)&baseA[c] = f2h2(o[mi][nt][0] * ilA, o[mi][nt][1] * ilA);
            *(unsigned*)&baseB[c] = f2h2(o[mi][nt][2] * ilB, o[mi][nt][3] * ilB);
        }
    }
}

// ============================================================================
// launcher
// ============================================================================
extern "C" void kernel_launch(void* const* d_in, const int* in_sizes, int n_in,
                              void* d_out, int out_size)
{
    const float* x         = (const float*)d_in[0];  // [32,512,512]
    const float* W_qkv     = (const float*)d_in[1];  // [512,1536]
    const float* rel_table = (const float*)d_in[2];  // [1025,64]
    const float* W_out     = (const float*)d_in[3];  // [512,512]
    const float* b_out     = (const float*)d_in[4];  // [512]
    float* out = (float*)d_out;                      // [32,512,512]

    unsigned short *xh, *wqkvT, *woutT, *ao;
    cudaGetSymbolAddress((void**)&xh,    g_xh);
    cudaGetSymbolAddress((void**)&wqkvT, g_wqkvT);
    cudaGetSymbolAddress((void**)&woutT, g_woutT);
    cudaGetSymbolAddress((void**)&ao,    g_ao);

    // 0. single-launch pre-convert
    cvt_all_kernel<<<CVT_XB + CVT_RB + CVT_QB + CVT_OB, 256>>>(
        x, rel_table, W_qkv, W_out);

    // 1. QKV projection (fp16 mma, 3 CTAs/SM, fused scatter; V transposed)
    cudaFuncSetAttribute(mm8_kernel<NQKV, 1>,
                         cudaFuncAttributeMaxDynamicSharedMemorySize, MM8_SMEM_BYTES);
    mm8_kernel<NQKV, 1><<<dim3(NQKV / 64, MROWS / 128), 128, MM8_SMEM_BYTES>>>(
        xh, wqkvT, nullptr, nullptr);

    // 2. fused fp16-mma attention (3 CTAs/SM, early-V pipeline)
    cudaFuncSetAttribute(attn8_kernel,
                         cudaFuncAttributeMaxDynamicSharedMemorySize, ATT8_SMEM_BYTES);
    attn8_kernel<<<dim3(BH, NSEQ / 64), 128, ATT8_SMEM_BYTES>>>();

    // 3. output projection (fp16 mma, 3 CTAs/SM, fused bias)
    cudaFuncSetAttribute(mm8_kernel<DMODEL, 0>,
                         cudaFuncAttributeMaxDynamicSharedMemorySize, MM8_SMEM_BYTES);
    mm8_kernel<DMODEL, 0><<<dim3(DMODEL / 64, MROWS / 128), 128, MM8_SMEM_BYTES>>>(
        ao, woutT, b_out, out);
}

// round 17
// speedup vs baseline: 1.0592x; 1.0592x over previous
#include <cuda_runtime.h>
#include <cuda_fp16.h>

// Problem constants
#define HEADS   8
#define DIMH    64
#define NSEQ    512
#define BATCH   32
#define DMODEL  512
#define BH      (BATCH*HEADS)        // 256
#define NQKV    (3*HEADS*DIMH)       // 1536
#define MROWS   (BATCH*NSEQ)         // 16384
#define ATT_SCALE 0.125f             // 64^-0.5

// ---------------- scratch (device globals; no cudaMalloc allowed) -----------
__device__ __align__(16) unsigned short g_q    [BH*NSEQ*DIMH];
__device__ __align__(16) unsigned short g_k    [BH*NSEQ*DIMH];
__device__ __align__(16) unsigned short g_vT   [BH*DIMH*NSEQ];    // [bh][d][n]
__device__ __align__(16) unsigned short g_ao   [BATCH*NSEQ*DMODEL];
__device__ __align__(16) unsigned short g_xh   [MROWS*DMODEL];
__device__ __align__(16) unsigned short g_wqkvT[NQKV*DMODEL];     // [N][K]
__device__ __align__(16) unsigned short g_woutT[DMODEL*DMODEL];   // [N][K]
__device__ __align__(16) unsigned short g_relh [1025*DIMH];

// ---------------------------------------------------------------------------
// helpers
// ---------------------------------------------------------------------------
__device__ __forceinline__ unsigned f2h2(float lo, float hi) {
    unsigned r;
    asm("cvt.rn.f16x2.f32 %0, %1, %2;" : "=r"(r) : "f"(hi), "f"(lo));
    return r;
}
__device__ __forceinline__ unsigned short f2h(float x) {
    unsigned short r;
    asm("cvt.rn.f16.f32 %0, %1;" : "=h"(r) : "f"(x));
    return r;
}

__device__ __forceinline__ void mma_f16(float c[4], const unsigned a[4],
                                        unsigned b0, unsigned b1) {
    asm volatile(
        "mma.sync.aligned.m16n8k16.row.col.f32.f16.f16.f32 "
        "{%0,%1,%2,%3}, {%4,%5,%6,%7}, {%8,%9}, {%0,%1,%2,%3};\n"
        : "+f"(c[0]), "+f"(c[1]), "+f"(c[2]), "+f"(c[3])
        : "r"(a[0]), "r"(a[1]), "r"(a[2]), "r"(a[3]), "r"(b0), "r"(b1));
}
#define MMAH mma_f16

__device__ __forceinline__ void cp16(void* smem_dst, const void* gsrc) {
    unsigned s = (unsigned)__cvta_generic_to_shared(smem_dst);
    asm volatile("cp.async.cg.shared.global [%0], [%1], 16;\n" :: "r"(s), "l"(gsrc));
}
__device__ __forceinline__ void cp_commit() {
    asm volatile("cp.async.commit_group;\n");
}
template<int Nq>
__device__ __forceinline__ void cp_wait() {
    asm volatile("cp.async.wait_group %0;\n" :: "n"(Nq));
}

// ============================================================================
// cvt_all: single launch handling all fp32->fp16 conversions (unchanged R15).
// ============================================================================
#define CVT_XB   8192
#define CVT_RB   65
#define CVT_QB   768
#define CVT_OB   256

__global__ void __launch_bounds__(256) cvt_all_kernel(
    const float* __restrict__ x, const float* __restrict__ rel,
    const float* __restrict__ Wq, const float* __restrict__ Wo)
{
    __shared__ float t[32][33];
    const int b   = blockIdx.x;
    const int tid = threadIdx.x;

    if (b < CVT_XB) {
        const int i = b * 256 + tid;
        float4 v = ((const float4*)x)[i];
        ((uint2*)g_xh)[i] = make_uint2(f2h2(v.x, v.y), f2h2(v.z, v.w));
        return;
    }
    if (b < CVT_XB + CVT_RB) {
        const int i = (b - CVT_XB) * 256 + tid;
        if (i < 1025 * DIMH / 4) {
            float4 v = ((const float4*)rel)[i];
            ((uint2*)g_relh)[i] = make_uint2(f2h2(v.x, v.y), f2h2(v.z, v.w));
        }
        return;
    }
    const float* src;
    unsigned short* dst;
    int R, C, bx, by;
    if (b < CVT_XB + CVT_RB + CVT_QB) {
        const int l = b - (CVT_XB + CVT_RB);
        src = Wq; dst = g_wqkvT; R = DMODEL; C = NQKV;
        bx = (l % 48) * 32; by = (l / 48) * 32;
    } else {
        const int l = b - (CVT_XB + CVT_RB + CVT_QB);
        src = Wo; dst = g_woutT; R = DMODEL; C = DMODEL;
        bx = (l % 16) * 32; by = (l / 16) * 32;
    }
    const int tx = tid & 31, ty = tid >> 5;
#pragma unroll
    for (int j = 0; j < 32; j += 8)
        t[ty + j][tx] = src[(size_t)(by + ty + j) * C + bx + tx];
    __syncthreads();
#pragma unroll
    for (int j = 0; j < 32; j += 8)
        dst[(size_t)(bx + ty + j) * R + by + tx] = f2h(t[tx][ty + j]);
}

// ============================================================================
// mm7: fp16 GEMM (R15 config — best measured).
// ============================================================================
#define MM7_STAGE_W (2 * 128 * 20)
#define MM7_SMEM_BYTES (4 * MM7_STAGE_W * 4)

template<int N, int SCAT>   // SCAT: 0=bias epilogue, 1=qkv scatter
__global__ void __launch_bounds__(128, 2) mm7_kernel(
    const unsigned short* __restrict__ A, const unsigned short* __restrict__ Bt,
    const float* __restrict__ bias, float* __restrict__ Cout)
{
    constexpr int K = 512;
    constexpr int ITERS = 16;      // K / 32
    extern __shared__ unsigned sm[];

    const int tid  = threadIdx.x;
    const int w    = tid >> 5, lane = tid & 31;
    const int g    = lane >> 2, tig = lane & 3;
    const int wm   = w >> 1, wn = w & 1;
    const int bm   = blockIdx.y * 128;
    const int bn   = blockIdx.x * 128;

    auto issue = [&](int it) {
        const int s  = it & 3;
        const int k0 = it * 32;                 // halves
        unsigned* As = sm + s * MM7_STAGE_W;
        unsigned* Bs = As + 128 * 20;
#pragma unroll
        for (int j = 0; j < 4; ++j) {
            const int c  = tid + j * 128;
            const int r  = c >> 2;
            const int ch = c & 3;
            cp16(&As[r * 20 + ch * 4], A  + (size_t)(bm + r) * K + k0 + ch * 8);
            cp16(&Bs[r * 20 + ch * 4], Bt + (size_t)(bn + r) * K + k0 + ch * 8);
        }
    };

    float acc[4][8][4];
#pragma unroll
    for (int mi = 0; mi < 4; ++mi)
#pragma unroll
        for (int ni = 0; ni < 8; ++ni)
#pragma unroll
            for (int e = 0; e < 4; ++e) acc[mi][ni][e] = 0.f;

    issue(0); cp_commit();
    issue(1); cp_commit();
    issue(2); cp_commit();

    for (int it = 0; it < ITERS; ++it) {
        const int cur = it & 3;
        cp_wait<2>();
        __syncthreads();

        if (it + 3 < ITERS) issue(it + 3);
        cp_commit();

        const unsigned* As = sm + cur * MM7_STAGE_W;
        const unsigned* Bs = As + 128 * 20;
#pragma unroll
        for (int kt = 0; kt < 2; ++kt) {
            unsigned af[4][4];
#pragma unroll
            for (int mi = 0; mi < 4; ++mi) {
                const int base = wm * 64 + mi * 16;
                af[mi][0] = As[(base + g    ) * 20 + kt * 8 + tig    ];
                af[mi][1] = As[(base + g + 8) * 20 + kt * 8 + tig    ];
                af[mi][2] = As[(base + g    ) * 20 + kt * 8 + tig + 4];
                af[mi][3] = As[(base + g + 8) * 20 + kt * 8 + tig + 4];
            }
#pragma unroll
            for (int ni = 0; ni < 8; ++ni) {
                const int nr = wn * 64 + ni * 8 + g;
                const unsigned b0 = Bs[nr * 20 + kt * 8 + tig    ];
                const unsigned b1 = Bs[nr * 20 + kt * 8 + tig + 4];
#pragma unroll
                for (int mi = 0; mi < 4; ++mi)
                    MMAH(acc[mi][ni], af[mi], b0, b1);
            }
        }
    }

    // ---- epilogue ----
    if (SCAT) {
        const int which = bn >> 9;
        if (which < 2) {
            unsigned short* dst = (which == 0) ? g_q : g_k;
#pragma unroll
            for (int mi = 0; mi < 4; ++mi) {
                const int r0  = bm + wm * 64 + mi * 16 + g;
                const int bb  = r0 >> 9;
                const int nn0 = r0 & 511;
#pragma unroll
                for (int ni = 0; ni < 8; ++ni) {
                    const int c  = bn + wn * 64 + ni * 8 + 2 * tig;
                    const int h  = (c & 511) >> 6;
                    const int dd = c & 63;
                    const size_t rowbase = (size_t)((bb << 3) + h) * NSEQ;
                    *(unsigned*)&dst[((rowbase + nn0    )) * DIMH + dd] =
                        f2h2(acc[mi][ni][0], acc[mi][ni][1]);
                    *(unsigned*)&dst[((rowbase + nn0 + 8)) * DIMH + dd] =
                        f2h2(acc[mi][ni][2], acc[mi][ni][3]);
                }
            }
        } else {
            __syncthreads();
            unsigned short* tsm = (unsigned short*)sm;   // 128 x 136 halves
#pragma unroll
            for (int mi = 0; mi < 4; ++mi) {
                const int lr = wm * 64 + mi * 16 + g;
#pragma unroll
                for (int ni = 0; ni < 8; ++ni) {
                    const int lc = wn * 64 + ni * 8 + 2 * tig;
                    tsm[(lc    ) * 136 + lr    ] = f2h(acc[mi][ni][0]);
                    tsm[(lc + 1) * 136 + lr    ] = f2h(acc[mi][ni][1]);
                    tsm[(lc    ) * 136 + lr + 8] = f2h(acc[mi][ni][2]);
                    tsm[(lc + 1) * 136 + lr + 8] = f2h(acc[mi][ni][3]);
                }
            }
            __syncthreads();
            const int lc  = tid;
            const int c   = bn + lc;
            const int h   = (c & 511) >> 6;
            const int dd  = c & 63;
            const int bb  = bm >> 9;
            const int nnb = bm & 511;
            unsigned short* dstp =
                g_vT + ((size_t)((bb << 3) + h) * DIMH + dd) * NSEQ + nnb;
#pragma unroll
            for (int u = 0; u < 16; ++u)
                *(uint4*)(dstp + u * 8) = *(const uint4*)(tsm + lc * 136 + u * 8);
        }
    } else {
#pragma unroll
        for (int mi = 0; mi < 4; ++mi) {
            const int r = bm + wm * 64 + mi * 16 + g;
#pragma unroll
            for (int ni = 0; ni < 8; ++ni) {
                const int c = bn + wn * 64 + ni * 8 + 2 * tig;
                const float2 bv = *(const float2*)&bias[c];
                *(float2*)&Cout[(size_t)r * N + c] =
                    make_float2(acc[mi][ni][0] + bv.x, acc[mi][ni][1] + bv.y);
                *(float2*)&Cout[(size_t)(r + 8) * N + c] =
                    make_float2(acc[mi][ni][2] + bv.x, acc[mi][ni][3] + bv.y);
            }
        }
    }
}

// ============================================================================
// attn9: register-resident P (C-frag of S == A-frag for PV, so pa = f2h2(s)),
// PV split across wn (kills the duplicated PV work of attn7/8), partial-O
// summed once at epilogue via pbs. Removes P smem roundtrip + both pair
// barriers. PB ping-pong halves unchanged (S2 of t+1 orders gather(t) before
// PB-overwrite). 3 CTAs/SM, early-V pipeline.
// ============================================================================
#define ATT9_SMEM_WORDS (2304 + 2304 + 4608 + 8448)
#define ATT9_SMEM_BYTES (ATT9_SMEM_WORDS * 4)

__global__ void __launch_bounds__(128, 3) attn9_kernel()
{
    extern __shared__ unsigned smu[];
    unsigned* rels  = smu;                    // 64 x 36 (Q staging alias)
    unsigned* ks    = smu + 2304;             // 64 x 36 (l-exchange alias)
    unsigned* vsbuf = smu + 4608;             // 2 x 64 x 36
    float*    pbs   = (float*)(smu + 9216);   // 64 x 132 (o-exchange alias)

    const int tid  = threadIdx.x;
    const int w    = tid >> 5;
    const int lane = tid & 31;
    const int g    = lane >> 2;
    const int tig  = lane & 3;
    const int wm   = w >> 1, wn = w & 1;

    const int bh = blockIdx.x;
    const int qb = blockIdx.y;
    const int i0 = qb * 64;
    const int rbase = wm * 32 + g;

    const unsigned short* qg = g_q  + ((size_t)bh * NSEQ + i0) * DIMH;
    const unsigned short* kg = g_k  + (size_t)bh * NSEQ * DIMH;
    const unsigned short* vg = g_vT + (size_t)bh * DIMH * NSEQ;
    const unsigned short* rg = g_relh;

    auto copy_tile = [&](unsigned* dst, const unsigned short* src, int srcstride) {
#pragma unroll
        for (int k = 0; k < 4; ++k) {
            const int c  = tid + k * 128;
            const int r  = c >> 3;
            const int ch = c & 7;
            cp16(&dst[r * 36 + ch * 4], src + (size_t)r * srcstride + ch * 8);
        }
    };

    auto issue_kr = [&](int t) {
        const int j0 = t * 64;
        copy_tile(ks, kg + (size_t)j0 * DIMH, 64);
        copy_tile(rels, rg + (size_t)(i0 + 449 - j0) * DIMH, 64);
    };
    auto issue_v = [&](int t) {
        copy_tile(vsbuf + (t & 1) * 2304, vg + t * 64, NSEQ);
    };

    // ---- stage Q ----
    copy_tile(rels, qg, 64);
    cp_commit();
    cp_wait<0>();
    __syncthreads();

    unsigned qa[2][4][4];
#pragma unroll
    for (int mi = 0; mi < 2; ++mi) {
        const int r0 = rbase + mi * 16;
#pragma unroll
        for (int kt = 0; kt < 4; ++kt) {
            qa[mi][kt][0] = rels[ r0      * 36 + kt * 8 + tig    ];
            qa[mi][kt][1] = rels[(r0 + 8) * 36 + kt * 8 + tig    ];
            qa[mi][kt][2] = rels[ r0      * 36 + kt * 8 + tig + 4];
            qa[mi][kt][3] = rels[(r0 + 8) * 36 + kt * 8 + tig + 4];
        }
    }
    __syncthreads();

    // ---- prologue: rel chunk(-1) -> pbs half 1 ----
    {
        copy_tile(rels, rg + (size_t)(i0 + 513) * DIMH, 64);
        cp_commit();
        cp_wait<0>();
        __syncthreads();
#pragma unroll
        for (int nt = 0; nt < 4; ++nt) {
            float a0[4] = {0.f,0.f,0.f,0.f}, a1[4] = {0.f,0.f,0.f,0.f};
            const int dr = wn * 32 + nt * 8 + g;
#pragma unroll
            for (int kt = 0; kt < 4; ++kt) {
                const unsigned b0 = rels[dr * 36 + kt * 8 + tig    ];
                const unsigned b1 = rels[dr * 36 + kt * 8 + tig + 4];
                MMAH(a0, qa[0][kt], b0, b1);
                MMAH(a1, qa[1][kt], b0, b1);
            }
            const int col = 64 + wn * 32 + nt * 8 + 2 * tig;
            *(float2*)&pbs[(rbase     ) * 132 + col] = make_float2(a0[0], a0[1]);
            *(float2*)&pbs[(rbase +  8) * 132 + col] = make_float2(a0[2], a0[3]);
            *(float2*)&pbs[(rbase + 16) * 132 + col] = make_float2(a1[0], a1[1]);
            *(float2*)&pbs[(rbase + 24) * 132 + col] = make_float2(a1[2], a1[3]);
        }
    }
    __syncthreads();

    issue_kr(0);
    issue_v(0);
    cp_commit();

    float lsum[2][2] = {{0.f, 0.f}, {0.f, 0.f}};
    float o[2][8][4];
#pragma unroll
    for (int mi = 0; mi < 2; ++mi)
#pragma unroll
        for (int nt = 0; nt < 8; ++nt)
#pragma unroll
            for (int e = 0; e < 4; ++e) o[mi][nt][e] = 0.f;

    for (int t = 0; t < 8; ++t) {
        const int h = t & 1;
        const unsigned* vs = vsbuf + h * 2304;

        cp_wait<0>();
        __syncthreads();               // S2: tiles t ready; all past PV(t-1)
                                       //     and all past gather(t-1) -> PB safe

        if (t + 1 < 8) { issue_v(t + 1); cp_commit(); }

        // ---- PB new chunk -> pbs half h ----
#pragma unroll
        for (int nt = 0; nt < 4; ++nt) {
            float a0[4] = {0.f,0.f,0.f,0.f}, a1[4] = {0.f,0.f,0.f,0.f};
            const int dr = wn * 32 + nt * 8 + g;
#pragma unroll
            for (int kt = 0; kt < 4; ++kt) {
                const unsigned b0 = rels[dr * 36 + kt * 8 + tig    ];
                const unsigned b1 = rels[dr * 36 + kt * 8 + tig + 4];
                MMAH(a0, qa[0][kt], b0, b1);
                MMAH(a1, qa[1][kt], b0, b1);
            }
            const int col = h * 64 + wn * 32 + nt * 8 + 2 * tig;
            *(float2*)&pbs[(rbase     ) * 132 + col] = make_float2(a0[0], a0[1]);
            *(float2*)&pbs[(rbase +  8) * 132 + col] = make_float2(a0[2], a0[3]);
            *(float2*)&pbs[(rbase + 16) * 132 + col] = make_float2(a1[0], a1[1]);
            *(float2*)&pbs[(rbase + 24) * 132 + col] = make_float2(a1[2], a1[3]);
        }

        // ---- QK (warp's 32 rows x its 32 j cols) ----
        float s[2][4][4];
#pragma unroll
        for (int nt = 0; nt < 4; ++nt) {
            const int jr = wn * 32 + nt * 8 + g;
#pragma unroll
            for (int mi = 0; mi < 2; ++mi)
                s[mi][nt][0] = s[mi][nt][1] = s[mi][nt][2] = s[mi][nt][3] = 0.f;
#pragma unroll
            for (int kt = 0; kt < 4; ++kt) {
                const unsigned b0 = ks[jr * 36 + kt * 8 + tig    ];
                const unsigned b1 = ks[jr * 36 + kt * 8 + tig + 4];
                MMAH(s[0][nt], qa[0][kt], b0, b1);
                MMAH(s[1][nt], qa[1][kt], b0, b1);
            }
        }
        __syncthreads();               // S3 (CTA): pbs half h visible; ks/rels free

        if (t + 1 < 8) { issue_kr(t + 1); cp_commit(); }

        // ---- bias gather + exp + partial sums (no barrier needed after) ----
#pragma unroll
        for (int mi = 0; mi < 2; ++mi) {
            const int iA = rbase + mi * 16;
            const int iB = iA + 8;
#pragma unroll
            for (int nt = 0; nt < 4; ++nt) {
                const int jj = wn * 32 + nt * 8 + 2 * tig;
                const int oA0 = iA - jj + 63, oA1 = oA0 - 1;
                const int oB0 = iB - jj + 63, oB1 = oB0 - 1;
                const int pA0 = ((h ^ (oA0 >> 6)) << 6) | (oA0 & 63);
                const int pA1 = ((h ^ (oA1 >> 6)) << 6) | (oA1 & 63);
                const int pB0 = ((h ^ (oB0 >> 6)) << 6) | (oB0 & 63);
                const int pB1 = ((h ^ (oB1 >> 6)) << 6) | (oB1 & 63);
                float e0 = __expf((s[mi][nt][0] + pbs[iA * 132 + pA0]) * ATT_SCALE);
                float e1 = __expf((s[mi][nt][1] + pbs[iA * 132 + pA1]) * ATT_SCALE);
                float e2 = __expf((s[mi][nt][2] + pbs[iB * 132 + pB0]) * ATT_SCALE);
                float e3 = __expf((s[mi][nt][3] + pbs[iB * 132 + pB1]) * ATT_SCALE);
                s[mi][nt][0] = e0; s[mi][nt][1] = e1;
                s[mi][nt][2] = e2; s[mi][nt][3] = e3;
                lsum[mi][0] += e0 + e1;
                lsum[mi][1] += e2 + e3;
            }
        }

        // ---- O += P @ V over the warp's own 32 j cols; P stays in regs.
        //      C-frag of S == A-frag for PV: pa = f2h2(s).           ----
#pragma unroll
        for (int kq = 0; kq < 2; ++kq) {
            unsigned pa[2][4];
#pragma unroll
            for (int mi = 0; mi < 2; ++mi) {
                pa[mi][0] = f2h2(s[mi][2*kq    ][0], s[mi][2*kq    ][1]);
                pa[mi][1] = f2h2(s[mi][2*kq    ][2], s[mi][2*kq    ][3]);
                pa[mi][2] = f2h2(s[mi][2*kq + 1][0], s[mi][2*kq + 1][1]);
                pa[mi][3] = f2h2(s[mi][2*kq + 1][2], s[mi][2*kq + 1][3]);
            }
#pragma unroll
            for (int nt = 0; nt < 8; ++nt) {
                const int dr = nt * 8 + g;     // d row of vT tile
                const unsigned b0 = vs[dr * 36 + wn * 16 + kq * 8 + tig    ];
                const unsigned b1 = vs[dr * 36 + wn * 16 + kq * 8 + tig + 4];
                MMAH(o[0][nt], pa[0], b0, b1);
                MMAH(o[1][nt], pa[1], b0, b1);
            }
        }
    }

    // ---- epilogue: sum O partials across wn pair, combine l, store ----
#pragma unroll
    for (int mi = 0; mi < 2; ++mi)
#pragma unroll
        for (int hf = 0; hf < 2; ++hf) {
            float v = lsum[mi][hf];
            v += __shfl_xor_sync(0xffffffffu, v, 1);
            v += __shfl_xor_sync(0xffffffffu, v, 2);
            lsum[mi][hf] = v;
        }

    __syncthreads();                   // all warps past final gather/PV
    float* obuf = pbs;                 // 2*32*64 floats (8448 avail)
    float* lsm  = (float*)ks;
    const int slot = (wm * 32 + lane) * 64;
    if (wn == 1) {
#pragma unroll
        for (int mi = 0; mi < 2; ++mi)
#pragma unroll
            for (int nt = 0; nt < 8; ++nt)
#pragma unroll
                for (int e = 0; e < 4; ++e)
                    obuf[slot + mi * 32 + nt * 4 + e] = o[mi][nt][e];
    }
    if (tig == 0) {
#pragma unroll
        for (int mi = 0; mi < 2; ++mi) {
            lsm[(rbase + mi * 16    ) * 2 + wn] = lsum[mi][0];
            lsm[(rbase + mi * 16 + 8) * 2 + wn] = lsum[mi][1];
        }
    }
    __syncthreads();

    if (wn == 0) {
        const int bb = bh >> 3, hh = bh & 7;
#pragma unroll
        for (int mi = 0; mi < 2; ++mi) {
            const int iA = rbase + mi * 16;
            const int iB = iA + 8;
            const float ilA = 1.f / (lsm[iA * 2] + lsm[iA * 2 + 1]);
            const float ilB = 1.f / (lsm[iB * 2] + lsm[iB * 2 + 1]);
            unsigned short* baseA = g_ao + ((size_t)bb * NSEQ + (i0 + iA)) * DMODEL + hh * DIMH;
            unsigned short* baseB = g_ao + ((size_t)bb * NSEQ + (i0 + iB)) * DMODEL + hh * DIMH;
#pragma unroll
            for (int nt = 0; nt < 8; ++nt) {
                const int c = nt * 8 + 2 * tig;
                const float o0 = o[mi][nt][0] + obuf[slot + mi * 32 + nt * 4 + 0];
                const float o1 = o[mi][nt][1] + obuf[slot + mi * 32 + nt * 4 + 1];
                const float o2 = o[mi][nt][2] + obuf[slot + mi * 32 + nt * 4 + 2];
                const float o3 = o[mi][nt][3] + obuf[slot + mi * 32 + nt * 4 + 3];
                *(unsigned*)&baseA[c] = f2h2(o0 * ilA, o1 * ilA);
                *(unsigned*)&baseB[c] = f2h2(o2 * ilB, o3 * ilB);
            }
        }
    }
}

// ============================================================================
// launcher
// ============================================================================
extern "C" void kernel_launch(void* const* d_in, const int* in_sizes, int n_in,
                              void* d_out, int out_size)
{
    const float* x         = (const float*)d_in[0];  // [32,512,512]
    const float* W_qkv     = (const float*)d_in[1];  // [512,1536]
    const float* rel_table = (const float*)d_in[2];  // [1025,64]
    const float* W_out     = (const float*)d_in[3];  // [512,512]
    const float* b_out     = (const float*)d_in[4];  // [512]
    float* out = (float*)d_out;                      // [32,512,512]

    unsigned short *xh, *wqkvT, *woutT, *ao;
    cudaGetSymbolAddress((void**)&xh,    g_xh);
    cudaGetSymbolAddress((void**)&wqkvT, g_wqkvT);
    cudaGetSymbolAddress((void**)&woutT, g_woutT);
    cudaGetSymbolAddress((void**)&ao,    g_ao);

    // 0. single-launch pre-convert
    cvt_all_kernel<<<CVT_XB + CVT_RB + CVT_QB + CVT_OB, 256>>>(
        x, rel_table, W_qkv, W_out);

    // 1. QKV projection (fp16 mma, fused scatter; V transposed)
    cudaFuncSetAttribute(mm7_kernel<NQKV, 1>,
                         cudaFuncAttributeMaxDynamicSharedMemorySize, MM7_SMEM_BYTES);
    mm7_kernel<NQKV, 1><<<dim3(NQKV / 128, MROWS / 128), 128, MM7_SMEM_BYTES>>>(
        xh, wqkvT, nullptr, nullptr);

    // 2. fused fp16-mma attention (3 CTAs/SM, register-P, split PV)
    cudaFuncSetAttribute(attn9_kernel,
                         cudaFuncAttributeMaxDynamicSharedMemorySize, ATT9_SMEM_BYTES);
    attn9_kernel<<<dim3(BH, NSEQ / 64), 128, ATT9_SMEM_BYTES>>>();

    // 3. output projection (fp16 mma, fused bias)
    cudaFuncSetAttribute(mm7_kernel<DMODEL, 0>,
                         cudaFuncAttributeMaxDynamicSharedMemorySize, MM7_SMEM_BYTES);
    mm7_kernel<DMODEL, 0><<<dim3(DMODEL / 128, MROWS / 128), 128, MM7_SMEM_BYTES>>>(
        ao, woutT, b_out, out);
}